// round 1
// baseline (speedup 1.0000x reference)
#include <cuda_runtime.h>
#include <math.h>

#define NB 8
#define NS 2048
#define ND 1024
#define NH1 512
#define NDH 128
#define NDV 512
#define NM (NB*NS)   // 16384

// scratch (device globals: allocation-free per harness rules)
__device__ float g_W12[ND*NDH];
__device__ float g_W46[ND*NDH];
__device__ float g_WSUM[NDV*NDV];
__device__ float g_Q2[(size_t)NM*NDH];
__device__ float g_K3[(size_t)NM*NDH];
__device__ float g_Q3[(size_t)NM*NDV];
__device__ float g_ATTN[(size_t)NM*NDV];

// ---------------------------------------------------------------------------
// Generic SGEMM: C[M,N] = (A (+ A2)) @ B   (row-major, BM=BN=128, BK=8, 8x8 micro)
// M % 128 == 0, N % 128 == 0, K % 8 == 0
// ---------------------------------------------------------------------------
template<bool FUSE>
__global__ __launch_bounds__(256) void sgemm128(
    const float* __restrict__ A, const float* __restrict__ A2,
    const float* __restrict__ Bm, float* __restrict__ C,
    int M, int N, int K)
{
    __shared__ float As[8][128];
    __shared__ float Bs[8][128];
    const int tid = threadIdx.x;
    const int tx = tid & 15, ty = tid >> 4;
    const int brow = blockIdx.x * 128, bcol = blockIdx.y * 128;

    float acc[8][8];
#pragma unroll
    for (int i = 0; i < 8; i++)
#pragma unroll
        for (int j = 0; j < 8; j++) acc[i][j] = 0.f;

    const int arow = tid >> 1;          // 0..127
    const int akp  = (tid & 1) << 2;    // 0 or 4
    const int brw  = tid >> 5;          // 0..7
    const int bc4  = (tid & 31) << 2;   // 0..124

    const float* Ap  = A + (size_t)(brow + arow) * K + akp;
    const float* A2p = FUSE ? (A2 + (size_t)(brow + arow) * K + akp) : nullptr;
    const float* Bp  = Bm + (size_t)brw * N + bcol + bc4;

    for (int k0 = 0; k0 < K; k0 += 8) {
        float4 a = *(const float4*)(Ap + k0);
        if (FUSE) {
            float4 a2 = *(const float4*)(A2p + k0);
            a.x += a2.x; a.y += a2.y; a.z += a2.z; a.w += a2.w;
        }
        As[akp+0][arow] = a.x; As[akp+1][arow] = a.y;
        As[akp+2][arow] = a.z; As[akp+3][arow] = a.w;
        *(float4*)&Bs[brw][bc4] = *(const float4*)(Bp + (size_t)k0 * N);
        __syncthreads();
#pragma unroll
        for (int k = 0; k < 8; k++) {
            float ra[8], rb[8];
            *(float4*)&ra[0] = *(const float4*)&As[k][ty*8];
            *(float4*)&ra[4] = *(const float4*)&As[k][ty*8+4];
            *(float4*)&rb[0] = *(const float4*)&Bs[k][tx*8];
            *(float4*)&rb[4] = *(const float4*)&Bs[k][tx*8+4];
#pragma unroll
            for (int i = 0; i < 8; i++)
#pragma unroll
                for (int j = 0; j < 8; j++)
                    acc[i][j] = fmaf(ra[i], rb[j], acc[i][j]);
        }
        __syncthreads();
    }
#pragma unroll
    for (int i = 0; i < 8; i++) {
        float* Cp = C + (size_t)(brow + ty*8 + i) * N + bcol + tx*8;
        *(float4*)Cp       = make_float4(acc[i][0], acc[i][1], acc[i][2], acc[i][3]);
        *(float4*)(Cp + 4) = make_float4(acc[i][4], acc[i][5], acc[i][6], acc[i][7]);
    }
}

// WSUM[r][c] = w7[r][c] + w7[r+512][c]
__global__ void wsum_kernel(const float* __restrict__ w7, float* __restrict__ ws)
{
    int i = blockIdx.x * blockDim.x + threadIdx.x;
    if (i < NDV*NDV) ws[i] = w7[i] + w7[i + NDV*NDV];
}

// ---------------------------------------------------------------------------
// Flash attention, causal. BM = BN = 64, DH=128, DV=512.
// Grid: (NS/64, NB). 256 threads. Dynamic smem ~209 KB (full V tile resident).
// Smem layouts transposed so inner-loop LDS are conflict-free/broadcast.
// ---------------------------------------------------------------------------
__global__ __launch_bounds__(256) void flash_attn(
    const float* __restrict__ Q2, const float* __restrict__ K3,
    const float* __restrict__ V, float* __restrict__ O)
{
    extern __shared__ float sm[];
    float* Qs   = sm;                 // [128][64]  Qs[k][q]   (dim-major)
    float* Ks   = Qs + 128*64;        // [128][64]  Ks[k][j]
    float* Ss   = Ks + 128*64;        // [64][64]   Ss[j][q]   (key-major)
    float* Vs   = Ss + 64*64;         // [64][512]  Vs[j][c]
    float* mrow = Vs + 64*512;        // [64]
    float* lrow = mrow + 64;          // [64]
    float* arow = lrow + 64;          // [64]

    const int b  = blockIdx.y;
    const int qt = (int)gridDim.x - 1 - (int)blockIdx.x;  // long blocks launch first
    const int q0 = qt * 64;
    const int tid = threadIdx.x;
    const float scale = 0.088388347648318447f;  // 1/sqrt(128)

    // load Q tile, transposed into Qs[k][q]
    const float* Qg = Q2 + ((size_t)b * NS + q0) * NDH;
    for (int t = tid; t < 2048; t += 256) {          // 2048 float4s
        int row = t >> 5, kk = (t & 31) << 2;
        float4 v4 = *(const float4*)(Qg + row * NDH + kk);
        Qs[(kk+0)*64+row] = v4.x; Qs[(kk+1)*64+row] = v4.y;
        Qs[(kk+2)*64+row] = v4.z; Qs[(kk+3)*64+row] = v4.w;
    }
    if (tid < 64) { mrow[tid] = -1e30f; lrow[tid] = 0.f; }

    // output accumulators: thread owns rows ry*4..+3, cols {cx*4 + k*64 + 0..3}
    const int ry = tid >> 4, cx = tid & 15;
    float acc[4][8][4];
#pragma unroll
    for (int i = 0; i < 4; i++)
#pragma unroll
        for (int k = 0; k < 8; k++)
#pragma unroll
            for (int c = 0; c < 4; c++) acc[i][k][c] = 0.f;

    for (int kt = 0; kt <= qt; kt++) {
        const int k0 = kt * 64;
        __syncthreads();  // protect Ss/Ks/Vs from prior-iteration readers

        // load K tile transposed, V tile flat (both tile regions are contiguous)
        const float* Kg = K3 + ((size_t)b * NS + k0) * NDH;
        for (int t = tid; t < 2048; t += 256) {
            int row = t >> 5, kk = (t & 31) << 2;
            float4 v4 = *(const float4*)(Kg + row * NDH + kk);
            Ks[(kk+0)*64+row] = v4.x; Ks[(kk+1)*64+row] = v4.y;
            Ks[(kk+2)*64+row] = v4.z; Ks[(kk+3)*64+row] = v4.w;
        }
        const float4* Vg4 = (const float4*)(V + ((size_t)b * NS + k0) * NDV);
        float4* Vs4 = (float4*)Vs;
        for (int t = tid; t < 8192; t += 256) Vs4[t] = Vg4[t];
        __syncthreads();

        // ---- QK^T: thread computes 4x4 micro-tile of S ----
        float sacc[4][4];
#pragma unroll
        for (int i = 0; i < 4; i++)
#pragma unroll
            for (int j = 0; j < 4; j++) sacc[i][j] = 0.f;

#pragma unroll 8
        for (int kk = 0; kk < 128; kk++) {
            float4 qv = *(const float4*)&Qs[kk*64 + ry*4];
            float4 kv = *(const float4*)&Ks[kk*64 + cx*4];
            float qa[4] = {qv.x, qv.y, qv.z, qv.w};
            float ka[4] = {kv.x, kv.y, kv.z, kv.w};
#pragma unroll
            for (int i = 0; i < 4; i++)
#pragma unroll
                for (int j = 0; j < 4; j++)
                    sacc[i][j] = fmaf(qa[i], ka[j], sacc[i][j]);
        }
        const bool diag = (kt == qt);
#pragma unroll
        for (int j = 0; j < 4; j++)
#pragma unroll
            for (int i = 0; i < 4; i++) {
                float s = sacc[i][j] * scale;
                if (diag && (cx*4 + j) > (ry*4 + i)) s = -1e30f;
                Ss[(cx*4+j)*64 + ry*4 + i] = s;
            }
        __syncthreads();

        // ---- online softmax: 4 threads per row, 16 cols each ----
        {
            int row = tid >> 2, g = tid & 3;
            float mx = -1e30f;
#pragma unroll
            for (int c = 0; c < 16; c++) mx = fmaxf(mx, Ss[(g*16+c)*64 + row]);
            mx = fmaxf(mx, __shfl_xor_sync(0xffffffffu, mx, 1));
            mx = fmaxf(mx, __shfl_xor_sync(0xffffffffu, mx, 2));
            float mold = mrow[row];
            float mnew = fmaxf(mold, mx);
            float al = __expf(mold - mnew);
            float sum = 0.f;
#pragma unroll
            for (int c = 0; c < 16; c++) {
                int idx = (g*16+c)*64 + row;
                float p = __expf(Ss[idx] - mnew);
                Ss[idx] = p;
                sum += p;
            }
            sum += __shfl_xor_sync(0xffffffffu, sum, 1);
            sum += __shfl_xor_sync(0xffffffffu, sum, 2);
            if (g == 0) {
                mrow[row] = mnew;
                lrow[row] = lrow[row] * al + sum;
                arow[row] = al;
            }
        }
        __syncthreads();

        // ---- rescale accumulators, then P @ V ----
        {
            float al[4];
#pragma unroll
            for (int i = 0; i < 4; i++) al[i] = arow[ry*4+i];
#pragma unroll
            for (int i = 0; i < 4; i++)
#pragma unroll
                for (int k = 0; k < 8; k++)
#pragma unroll
                    for (int c = 0; c < 4; c++) acc[i][k][c] *= al[i];

#pragma unroll 2
            for (int j = 0; j < 64; j++) {
                float4 pv4 = *(const float4*)&Ss[j*64 + ry*4];
                float pa[4] = {pv4.x, pv4.y, pv4.z, pv4.w};
#pragma unroll
                for (int k = 0; k < 8; k++) {
                    float4 vv = *(const float4*)&Vs[j*512 + k*64 + cx*4];
#pragma unroll
                    for (int i = 0; i < 4; i++) {
                        acc[i][k][0] = fmaf(pa[i], vv.x, acc[i][k][0]);
                        acc[i][k][1] = fmaf(pa[i], vv.y, acc[i][k][1]);
                        acc[i][k][2] = fmaf(pa[i], vv.z, acc[i][k][2]);
                        acc[i][k][3] = fmaf(pa[i], vv.w, acc[i][k][3]);
                    }
                }
            }
        }
    }

    // epilogue: normalize and store
    float linv[4];
#pragma unroll
    for (int i = 0; i < 4; i++) linv[i] = 1.f / lrow[ry*4+i];
    float* Og = O + ((size_t)b * NS + q0) * NDV;
#pragma unroll
    for (int i = 0; i < 4; i++)
#pragma unroll
        for (int k = 0; k < 8; k++) {
            float4 r = make_float4(acc[i][k][0]*linv[i], acc[i][k][1]*linv[i],
                                   acc[i][k][2]*linv[i], acc[i][k][3]*linv[i]);
            *(float4*)(Og + (size_t)(ry*4+i)*NDV + k*64 + cx*4) = r;
        }
}

// ---------------------------------------------------------------------------
extern "C" void kernel_launch(void* const* d_in, const int* in_sizes, int n_in,
                              void* d_out, int out_size)
{
    const float* q  = (const float*)d_in[0];
    const float* k  = (const float*)d_in[1];
    const float* v  = (const float*)d_in[2];
    const float* w1 = (const float*)d_in[3];
    const float* w2 = (const float*)d_in[4];
    const float* w3 = (const float*)d_in[5];
    const float* w4 = (const float*)d_in[6];
    const float* w6 = (const float*)d_in[7];
    const float* w7 = (const float*)d_in[8];
    float* out = (float*)d_out;

    float *W12, *W46, *WSUM, *Q2, *K3, *Q3, *ATTN;
    cudaGetSymbolAddress((void**)&W12,  g_W12);
    cudaGetSymbolAddress((void**)&W46,  g_W46);
    cudaGetSymbolAddress((void**)&WSUM, g_WSUM);
    cudaGetSymbolAddress((void**)&Q2,   g_Q2);
    cudaGetSymbolAddress((void**)&K3,   g_K3);
    cudaGetSymbolAddress((void**)&Q3,   g_Q3);
    cudaGetSymbolAddress((void**)&ATTN, g_ATTN);

    // weight prep:  W12 = w1@w2, W46 = w4@w6, WSUM = w7_top + w7_bot
    sgemm128<false><<<dim3(ND/128, NDH/128), 256>>>(w1, nullptr, w2, W12, ND, NDH, NH1);
    sgemm128<false><<<dim3(ND/128, NDH/128), 256>>>(w4, nullptr, w6, W46, ND, NDH, NH1);
    wsum_kernel<<<(NDV*NDV)/256, 256>>>(w7, WSUM);

    // projections:  q2 = q@W12, k3 = k@W46, q3 = q@w3
    sgemm128<false><<<dim3(NM/128, NDH/128), 256>>>(q, nullptr, W12, Q2, NM, NDH, ND);
    sgemm128<false><<<dim3(NM/128, NDH/128), 256>>>(k, nullptr, W46, K3, NM, NDH, ND);
    sgemm128<false><<<dim3(NM/128, NDV/128), 256>>>(q, nullptr, w3, Q3, NM, NDV, ND);

    // causal flash attention
    size_t smem = (size_t)(128*64 + 128*64 + 64*64 + 64*512 + 192) * sizeof(float);
    cudaFuncSetAttribute(flash_attn, cudaFuncAttributeMaxDynamicSharedMemorySize, (int)smem);
    flash_attn<<<dim3(NS/64, NB), 256, smem>>>(Q2, K3, v, ATTN);

    // final: out = (attn + q3) @ WSUM
    sgemm128<true><<<dim3(NM/128, NDV/128), 256>>>(ATTN, Q3, WSUM, out, NM, NDV, NDV);
}

// round 3
// speedup vs baseline: 2.6079x; 2.6079x over previous
#include <cuda_runtime.h>
#include <math.h>
#include <stdint.h>

#define NB 8
#define NS 2048
#define ND 1024
#define NH1 512
#define NDH 128
#define NDV 512
#define NM (NB*NS)   // 16384

// scratch (device globals: allocation-free per harness rules)
__device__ float g_W12[ND*NDH];
__device__ float g_W46[ND*NDH];
__device__ float g_WSUM[NDV*NDV];
__device__ float g_Q2[(size_t)NM*NDH];
__device__ float g_K3[(size_t)NM*NDH];
__device__ float g_Q3[(size_t)NM*NDV];
__device__ float g_ATTN[(size_t)NM*NDV];

// ---------------------------------------------------------------------------
// helpers
// ---------------------------------------------------------------------------
__device__ __forceinline__ float to_tf32(float x) {
    float r;
    asm("cvt.rna.tf32.f32 %0, %1;" : "=f"(r) : "f"(x));
    return r;
}
__device__ __forceinline__ float4 to_tf32_4(float4 v) {
    v.x = to_tf32(v.x); v.y = to_tf32(v.y);
    v.z = to_tf32(v.z); v.w = to_tf32(v.w);
    return v;
}
__device__ __forceinline__ uint32_t fbits(float x) { return __float_as_uint(x); }

// D += A@B  (m16n8k8, tf32, row.col)
__device__ __forceinline__ void mma8(float d[4], const uint32_t a[4],
                                     uint32_t b0, uint32_t b1) {
    asm volatile(
        "mma.sync.aligned.m16n8k8.row.col.f32.tf32.tf32.f32 "
        "{%0,%1,%2,%3},{%4,%5,%6,%7},{%8,%9},{%0,%1,%2,%3};"
        : "+f"(d[0]), "+f"(d[1]), "+f"(d[2]), "+f"(d[3])
        : "r"(a[0]), "r"(a[1]), "r"(a[2]), "r"(a[3]), "r"(b0), "r"(b1));
}

// ---------------------------------------------------------------------------
// TF32 GEMM: C[M,N] = (A (+A2)) @ B   row-major; tile 128x128, BK=16
// 256 threads = 8 warps (2m x 4n), warp tile 64x32, mma m16n8k8
// ---------------------------------------------------------------------------
#define APITCH 136   // 136 % 32 == 8 -> conflict-free (8*lr + lq) fragment pattern
template<bool FUSE>
__global__ __launch_bounds__(256, 2) void gemm_tf32(
    const float* __restrict__ A, const float* __restrict__ A2,
    const float* __restrict__ Bm, float* __restrict__ C,
    int M, int N, int K)
{
    __shared__ float As[2][16][APITCH];
    __shared__ float Bs[2][16][APITCH];

    const int tid  = threadIdx.x;
    const int lane = tid & 31;
    const int w    = tid >> 5;
    const int lq   = lane >> 2;     // 0..7
    const int lr   = lane & 3;      // 0..3
    const int wm   = w >> 2;        // 0..1
    const int wn   = w & 3;         // 0..3
    const int brow = blockIdx.x * 128, bcol = blockIdx.y * 128;

    // A-load mapping: 512 float4s; thread handles f = tid, tid+256
    const int ar0 = tid >> 2,        akc0 = (tid & 3) << 2;
    const int ar1 = (tid + 256) >> 2, akc1 = ((tid + 256) & 3) << 2;
    // B-load mapping
    const int bk0 = tid >> 5,        bnc0 = (tid & 31) << 2;
    const int bk1 = (tid + 256) >> 5, bnc1 = ((tid + 256) & 31) << 2;

    const float* Ap0  = A  + (size_t)(brow + ar0) * K + akc0;
    const float* Ap1  = A  + (size_t)(brow + ar1) * K + akc1;
    const float* A2p0 = FUSE ? (A2 + (size_t)(brow + ar0) * K + akc0) : nullptr;
    const float* A2p1 = FUSE ? (A2 + (size_t)(brow + ar1) * K + akc1) : nullptr;
    const float* Bp0  = Bm + (size_t)bk0 * N + bcol + bnc0;
    const float* Bp1  = Bm + (size_t)bk1 * N + bcol + bnc1;

    float acc[4][4][4];
#pragma unroll
    for (int mt = 0; mt < 4; mt++)
#pragma unroll
        for (int nt = 0; nt < 4; nt++)
#pragma unroll
            for (int i = 0; i < 4; i++) acc[mt][nt][i] = 0.f;

    const int nk = K / 16;

    // prologue: stage 0 into buf 0
    {
        float4 a0 = *(const float4*)Ap0;
        float4 a1 = *(const float4*)Ap1;
        if (FUSE) {
            float4 e0 = *(const float4*)A2p0, e1 = *(const float4*)A2p1;
            a0.x += e0.x; a0.y += e0.y; a0.z += e0.z; a0.w += e0.w;
            a1.x += e1.x; a1.y += e1.y; a1.z += e1.z; a1.w += e1.w;
        }
        a0 = to_tf32_4(a0); a1 = to_tf32_4(a1);
        As[0][akc0+0][ar0] = a0.x; As[0][akc0+1][ar0] = a0.y;
        As[0][akc0+2][ar0] = a0.z; As[0][akc0+3][ar0] = a0.w;
        As[0][akc1+0][ar1] = a1.x; As[0][akc1+1][ar1] = a1.y;
        As[0][akc1+2][ar1] = a1.z; As[0][akc1+3][ar1] = a1.w;
        float4 b0 = to_tf32_4(*(const float4*)Bp0);
        float4 b1 = to_tf32_4(*(const float4*)Bp1);
        *(float4*)&Bs[0][bk0][bnc0] = b0;
        *(float4*)&Bs[0][bk1][bnc1] = b1;
    }
    __syncthreads();

    for (int kt = 0; kt < nk; kt++) {
        const int buf = kt & 1;
        float4 pa0, pa1, pb0, pb1;
        const bool more = (kt + 1 < nk);
        if (more) {
            const int ko = (kt + 1) * 16;
            pa0 = *(const float4*)(Ap0 + ko);
            pa1 = *(const float4*)(Ap1 + ko);
            if (FUSE) {
                float4 e0 = *(const float4*)(A2p0 + ko);
                float4 e1 = *(const float4*)(A2p1 + ko);
                pa0.x += e0.x; pa0.y += e0.y; pa0.z += e0.z; pa0.w += e0.w;
                pa1.x += e1.x; pa1.y += e1.y; pa1.z += e1.z; pa1.w += e1.w;
            }
            pb0 = *(const float4*)(Bp0 + (size_t)ko * N);
            pb1 = *(const float4*)(Bp1 + (size_t)ko * N);
        }

        // compute on buf
#pragma unroll
        for (int ks = 0; ks < 2; ks++) {
            const int k = ks * 8;
            uint32_t af[4][4], bf[4][2];
#pragma unroll
            for (int mt = 0; mt < 4; mt++) {
                const int bm = wm * 64 + mt * 16;
                af[mt][0] = fbits(As[buf][k + lr    ][bm + lq    ]);
                af[mt][1] = fbits(As[buf][k + lr    ][bm + lq + 8]);
                af[mt][2] = fbits(As[buf][k + 4 + lr][bm + lq    ]);
                af[mt][3] = fbits(As[buf][k + 4 + lr][bm + lq + 8]);
            }
#pragma unroll
            for (int nt = 0; nt < 4; nt++) {
                const int bn = wn * 32 + nt * 8;
                bf[nt][0] = fbits(Bs[buf][k + lr    ][bn + lq]);
                bf[nt][1] = fbits(Bs[buf][k + 4 + lr][bn + lq]);
            }
#pragma unroll
            for (int mt = 0; mt < 4; mt++)
#pragma unroll
                for (int nt = 0; nt < 4; nt++)
                    mma8(acc[mt][nt], af[mt], bf[nt][0], bf[nt][1]);
        }

        if (more) {
            const int nb = buf ^ 1;
            pa0 = to_tf32_4(pa0); pa1 = to_tf32_4(pa1);
            As[nb][akc0+0][ar0] = pa0.x; As[nb][akc0+1][ar0] = pa0.y;
            As[nb][akc0+2][ar0] = pa0.z; As[nb][akc0+3][ar0] = pa0.w;
            As[nb][akc1+0][ar1] = pa1.x; As[nb][akc1+1][ar1] = pa1.y;
            As[nb][akc1+2][ar1] = pa1.z; As[nb][akc1+3][ar1] = pa1.w;
            *(float4*)&Bs[nb][bk0][bnc0] = to_tf32_4(pb0);
            *(float4*)&Bs[nb][bk1][bnc1] = to_tf32_4(pb1);
            __syncthreads();
        }
    }

    // epilogue
#pragma unroll
    for (int mt = 0; mt < 4; mt++) {
        const int r0 = brow + wm * 64 + mt * 16 + lq;
#pragma unroll
        for (int nt = 0; nt < 4; nt++) {
            const int col = bcol + wn * 32 + nt * 8 + lr * 2;
            *(float2*)(C + (size_t)r0 * N + col)       = make_float2(acc[mt][nt][0], acc[mt][nt][1]);
            *(float2*)(C + (size_t)(r0 + 8) * N + col) = make_float2(acc[mt][nt][2], acc[mt][nt][3]);
        }
    }
}

// WSUM[r][c] = w7[r][c] + w7[r+512][c]
__global__ void wsum_kernel(const float* __restrict__ w7, float* __restrict__ ws)
{
    int i = blockIdx.x * blockDim.x + threadIdx.x;
    if (i < NDV*NDV) ws[i] = w7[i] + w7[i + NDV*NDV];
}

// ---------------------------------------------------------------------------
// Flash attention (causal) with tf32 mma. BM=BN=64, DH=128, DV=512.
// 256 threads. Full V tile (64x512) resident in smem.
//   QK warps: 4(m) x 2(n); PV warps: 2(m) x 4(n)
// ---------------------------------------------------------------------------
#define QPITCH 132   // q*132+r pattern: 132%32=4 -> (4lq+lr) distinct
#define PPITCH 68    // 68%32=4  -> (4lq+lr) distinct
#define VPITCH 520   // r*520+q pattern: 520%32=8 -> (8lr+lq) distinct

__global__ __launch_bounds__(256) void flash_attn_tf32(
    const float* __restrict__ Q2, const float* __restrict__ K3,
    const float* __restrict__ V, float* __restrict__ O)
{
    extern __shared__ float sm[];
    float* Qs   = sm;                       // [64][132]
    float* Ks   = Qs + 64 * QPITCH;         // [64][132]
    float* Ps   = Ks + 64 * QPITCH;         // [64][68]
    float* Vs   = Ps + 64 * PPITCH;         // [64][520]
    float* mrow = Vs + 64 * VPITCH;         // [64]
    float* lrow = mrow + 64;                // [64]
    float* arow = lrow + 64;                // [64]

    const int b   = blockIdx.y;
    const int qt  = (int)gridDim.x - 1 - (int)blockIdx.x;  // long blocks first
    const int q0  = qt * 64;
    const int tid = threadIdx.x;
    const int lane = tid & 31, w = tid >> 5;
    const int lq = lane >> 2, lr = lane & 3;
    const int wmQ = w >> 1, wnQ = w & 1;   // QK: 4m x 2n
    const int wmP = w >> 2, wnP = w & 3;   // PV: 2m x 4n
    const float scale = 0.088388347648318447f;  // 1/sqrt(128)

    // load Q tile (tf32)
    const float* Qg = Q2 + ((size_t)b * NS + q0) * NDH;
    for (int f = tid; f < 2048; f += 256) {
        int row = f >> 5, kc = (f & 31) << 2;
        *(float4*)&Qs[row * QPITCH + kc] = to_tf32_4(*(const float4*)(Qg + row * NDH + kc));
    }
    if (tid < 64) { mrow[tid] = -1e30f; lrow[tid] = 0.f; }

    float oacc[2][16][4];
#pragma unroll
    for (int mt = 0; mt < 2; mt++)
#pragma unroll
        for (int nt = 0; nt < 16; nt++)
#pragma unroll
            for (int i = 0; i < 4; i++) oacc[mt][nt][i] = 0.f;

    for (int kt = 0; kt <= qt; kt++) {
        const int k0 = kt * 64;
        __syncthreads();   // prev iteration's PV readers done with Ks/Vs/Ps

        const float* Kg = K3 + ((size_t)b * NS + k0) * NDH;
        for (int f = tid; f < 2048; f += 256) {
            int row = f >> 5, kc = (f & 31) << 2;
            *(float4*)&Ks[row * QPITCH + kc] = to_tf32_4(*(const float4*)(Kg + row * NDH + kc));
        }
        const float* Vg = V + ((size_t)b * NS + k0) * NDV;
        for (int f = tid; f < 8192; f += 256) {
            int row = f >> 7, nc = (f & 127) << 2;
            *(float4*)&Vs[row * VPITCH + nc] = to_tf32_4(*(const float4*)(Vg + row * NDV + nc));
        }
        __syncthreads();

        // ---- S = Q @ K^T  (warp: 16 rows x 32 cols) ----
        float sacc[4][4];
#pragma unroll
        for (int nt = 0; nt < 4; nt++)
#pragma unroll
            for (int i = 0; i < 4; i++) sacc[nt][i] = 0.f;

#pragma unroll
        for (int ks = 0; ks < 16; ks++) {
            const int k = ks * 8;
            uint32_t af[4];
            const int rq = (wmQ * 16 + lq) * QPITCH;
            af[0] = fbits(Qs[rq            + k + lr]);
            af[1] = fbits(Qs[rq + 8*QPITCH + k + lr]);
            af[2] = fbits(Qs[rq            + k + 4 + lr]);
            af[3] = fbits(Qs[rq + 8*QPITCH + k + 4 + lr]);
#pragma unroll
            for (int nt = 0; nt < 4; nt++) {
                const int rk = (wnQ * 32 + nt * 8 + lq) * QPITCH;
                uint32_t b0 = fbits(Ks[rk + k + lr]);
                uint32_t b1 = fbits(Ks[rk + k + 4 + lr]);
                mma8(sacc[nt], af, b0, b1);
            }
        }
        // scale + causal mask + store to Ps (fp32)
        {
            const bool diag = (kt == qt);
            const int rloc0 = wmQ * 16 + lq;
            const int grow0 = q0 + rloc0, grow1 = grow0 + 8;
#pragma unroll
            for (int nt = 0; nt < 4; nt++) {
                const int col = wnQ * 32 + nt * 8 + lr * 2;
                const int gc0 = k0 + col, gc1 = gc0 + 1;
                float v0 = sacc[nt][0] * scale;
                float v1 = sacc[nt][1] * scale;
                float v2 = sacc[nt][2] * scale;
                float v3 = sacc[nt][3] * scale;
                if (diag) {
                    if (gc0 > grow0) v0 = -1e30f;
                    if (gc1 > grow0) v1 = -1e30f;
                    if (gc0 > grow1) v2 = -1e30f;
                    if (gc1 > grow1) v3 = -1e30f;
                }
                Ps[rloc0 * PPITCH + col]           = v0;
                Ps[rloc0 * PPITCH + col + 1]       = v1;
                Ps[(rloc0 + 8) * PPITCH + col]     = v2;
                Ps[(rloc0 + 8) * PPITCH + col + 1] = v3;
            }
        }
        __syncthreads();

        // ---- online softmax on Ps (4 threads/row, 16 cols each) ----
        {
            const int row = tid >> 2, g = tid & 3;
            float mx = -1e30f;
#pragma unroll
            for (int c = 0; c < 16; c++) mx = fmaxf(mx, Ps[row * PPITCH + g * 16 + c]);
            mx = fmaxf(mx, __shfl_xor_sync(0xffffffffu, mx, 1));
            mx = fmaxf(mx, __shfl_xor_sync(0xffffffffu, mx, 2));
            const float mold = mrow[row];
            const float mnew = fmaxf(mold, mx);
            const float al   = __expf(mold - mnew);
            float sum = 0.f;
#pragma unroll
            for (int c = 0; c < 16; c++) {
                const int idx = row * PPITCH + g * 16 + c;
                float p = __expf(Ps[idx] - mnew);
                Ps[idx] = to_tf32(p);
                sum += p;
            }
            sum += __shfl_xor_sync(0xffffffffu, sum, 1);
            sum += __shfl_xor_sync(0xffffffffu, sum, 2);
            if (g == 0) {
                mrow[row] = mnew;
                lrow[row] = lrow[row] * al + sum;
                arow[row] = al;
            }
        }
        __syncthreads();

        // ---- rescale O accumulators, then O += P @ V ----
        {
            const int rb = wmP * 32;
            const float al00 = arow[rb + lq];
            const float al01 = arow[rb + lq + 8];
            const float al10 = arow[rb + 16 + lq];
            const float al11 = arow[rb + 16 + lq + 8];
#pragma unroll
            for (int nt = 0; nt < 16; nt++) {
                oacc[0][nt][0] *= al00; oacc[0][nt][1] *= al00;
                oacc[0][nt][2] *= al01; oacc[0][nt][3] *= al01;
                oacc[1][nt][0] *= al10; oacc[1][nt][1] *= al10;
                oacc[1][nt][2] *= al11; oacc[1][nt][3] *= al11;
            }
#pragma unroll
            for (int ks = 0; ks < 8; ks++) {
                const int k = ks * 8;
                uint32_t af[2][4];
#pragma unroll
                for (int mt = 0; mt < 2; mt++) {
                    const int rp = (rb + mt * 16 + lq) * PPITCH;
                    af[mt][0] = fbits(Ps[rp             + k + lr]);
                    af[mt][1] = fbits(Ps[rp + 8*PPITCH  + k + lr]);
                    af[mt][2] = fbits(Ps[rp             + k + 4 + lr]);
                    af[mt][3] = fbits(Ps[rp + 8*PPITCH  + k + 4 + lr]);
                }
#pragma unroll
                for (int nt = 0; nt < 16; nt++) {
                    const int cb = wnP * 128 + nt * 8 + lq;
                    uint32_t b0 = fbits(Vs[(k + lr) * VPITCH + cb]);
                    uint32_t b1 = fbits(Vs[(k + 4 + lr) * VPITCH + cb]);
                    mma8(oacc[0][nt], af[0], b0, b1);
                    mma8(oacc[1][nt], af[1], b0, b1);
                }
            }
        }
    }

    __syncthreads();
    // epilogue: normalize and store
    {
        const int rb = wmP * 32;
        float li[2][2];
        li[0][0] = 1.f / lrow[rb + lq];
        li[0][1] = 1.f / lrow[rb + lq + 8];
        li[1][0] = 1.f / lrow[rb + 16 + lq];
        li[1][1] = 1.f / lrow[rb + 16 + lq + 8];
#pragma unroll
        for (int mt = 0; mt < 2; mt++) {
            const int gr = q0 + rb + mt * 16 + lq;
#pragma unroll
            for (int nt = 0; nt < 16; nt++) {
                const int col = wnP * 128 + nt * 8 + lr * 2;
                *(float2*)(O + ((size_t)b * NS + gr) * NDV + col) =
                    make_float2(oacc[mt][nt][0] * li[mt][0], oacc[mt][nt][1] * li[mt][0]);
                *(float2*)(O + ((size_t)b * NS + gr + 8) * NDV + col) =
                    make_float2(oacc[mt][nt][2] * li[mt][1], oacc[mt][nt][3] * li[mt][1]);
            }
        }
    }
}

// ---------------------------------------------------------------------------
extern "C" void kernel_launch(void* const* d_in, const int* in_sizes, int n_in,
                              void* d_out, int out_size)
{
    const float* q  = (const float*)d_in[0];
    const float* k  = (const float*)d_in[1];
    const float* v  = (const float*)d_in[2];
    const float* w1 = (const float*)d_in[3];
    const float* w2 = (const float*)d_in[4];
    const float* w3 = (const float*)d_in[5];
    const float* w4 = (const float*)d_in[6];
    const float* w6 = (const float*)d_in[7];
    const float* w7 = (const float*)d_in[8];
    float* out = (float*)d_out;

    // cache symbol addresses + one-time attribute setup across calls
    static float *W12 = nullptr, *W46, *WSUM, *Q2, *K3, *Q3, *ATTN;
    static bool init_done = false;
    if (!init_done) {
        cudaGetSymbolAddress((void**)&W12,  g_W12);
        cudaGetSymbolAddress((void**)&W46,  g_W46);
        cudaGetSymbolAddress((void**)&WSUM, g_WSUM);
        cudaGetSymbolAddress((void**)&Q2,   g_Q2);
        cudaGetSymbolAddress((void**)&K3,   g_K3);
        cudaGetSymbolAddress((void**)&Q3,   g_Q3);
        cudaGetSymbolAddress((void**)&ATTN, g_ATTN);
        size_t smem_attr = (size_t)(64*QPITCH + 64*QPITCH + 64*PPITCH + 64*VPITCH + 192) * sizeof(float);
        cudaFuncSetAttribute(flash_attn_tf32, cudaFuncAttributeMaxDynamicSharedMemorySize, (int)smem_attr);
        init_done = true;
    }

    // weight prep:  W12 = w1@w2, W46 = w4@w6, WSUM = w7_top + w7_bot
    gemm_tf32<false><<<dim3(ND/128, NDH/128), 256>>>(w1, nullptr, w2, W12, ND, NDH, NH1);
    gemm_tf32<false><<<dim3(ND/128, NDH/128), 256>>>(w4, nullptr, w6, W46, ND, NDH, NH1);
    wsum_kernel<<<(NDV*NDV)/256, 256>>>(w7, WSUM);

    // projections:  q2 = q@W12, k3 = k@W46, q3 = q@w3
    gemm_tf32<false><<<dim3(NM/128, NDH/128), 256>>>(q, nullptr, W12, Q2, NM, NDH, ND);
    gemm_tf32<false><<<dim3(NM/128, NDH/128), 256>>>(k, nullptr, W46, K3, NM, NDH, ND);
    gemm_tf32<false><<<dim3(NM/128, NDV/128), 256>>>(q, nullptr, w3, Q3, NM, NDV, ND);

    // causal flash attention (tf32 tensor cores)
    size_t smem = (size_t)(64*QPITCH + 64*QPITCH + 64*PPITCH + 64*VPITCH + 192) * sizeof(float);
    flash_attn_tf32<<<dim3(NS/64, NB), 256, smem>>>(Q2, K3, v, ATTN);

    // final: out = (attn + q3) @ WSUM
    gemm_tf32<true><<<dim3(NM/128, NDV/128), 256>>>(ATTN, Q3, WSUM, out, NM, NDV, NDV);
}

// round 4
// speedup vs baseline: 3.6236x; 1.3895x over previous
#include <cuda_runtime.h>
#include <math.h>
#include <stdint.h>

#define NB 8
#define NS 2048
#define ND 1024
#define NH1 512
#define NDH 128
#define NDV 512
#define NDOUT 512
#define NM (NB*NS)   // 16384

// scratch (device globals: allocation-free per harness rules)
__device__ float g_W12[ND*NDH];
__device__ float g_W46[ND*NDH];
__device__ float g_Q2[(size_t)NM*NDH];
__device__ float g_K3[(size_t)NM*NDH];
__device__ float g_Q3[(size_t)NM*NDV];
__device__ float g_ATTN[(size_t)NM*NDV];

// ---------------------------------------------------------------------------
// helpers
// ---------------------------------------------------------------------------
__device__ __forceinline__ float to_tf32(float x) {
    float r;
    asm("cvt.rna.tf32.f32 %0, %1;" : "=f"(r) : "f"(x));
    return r;
}
__device__ __forceinline__ float4 to_tf32_4(float4 v) {
    v.x = to_tf32(v.x); v.y = to_tf32(v.y);
    v.z = to_tf32(v.z); v.w = to_tf32(v.w);
    return v;
}
__device__ __forceinline__ uint32_t fbits(float x) { return __float_as_uint(x); }

// D += A@B  (m16n8k8, tf32, row.col)
__device__ __forceinline__ void mma8(float d[4], const uint32_t a[4],
                                     uint32_t b0, uint32_t b1) {
    asm volatile(
        "mma.sync.aligned.m16n8k8.row.col.f32.tf32.tf32.f32 "
        "{%0,%1,%2,%3},{%4,%5,%6,%7},{%8,%9},{%0,%1,%2,%3};"
        : "+f"(d[0]), "+f"(d[1]), "+f"(d[2]), "+f"(d[3])
        : "r"(a[0]), "r"(a[1]), "r"(a[2]), "r"(a[3]), "r"(b0), "r"(b1));
}

// ---------------------------------------------------------------------------
// TF32 GEMM body: C[*,N] tile at (brow,bcol) = (A (+A2)) @ (B (+B2))
// row-major; tile 128x128, BK=16, 256 threads = 8 warps (2m x 4n)
// ---------------------------------------------------------------------------
#define APITCH 136   // 136 % 32 == 8 -> conflict-free (8*lr + lq) fragment pattern

template<bool FUSEA, bool FUSEB>
__device__ __forceinline__ void gemm_body(
    float (*As)[16][APITCH], float (*Bs)[16][APITCH],
    const float* __restrict__ A, const float* __restrict__ A2,
    const float* __restrict__ Bm, const float* __restrict__ B2,
    float* __restrict__ C, int N, int K, int brow, int bcol)
{
    const int tid  = threadIdx.x;
    const int lane = tid & 31;
    const int w    = tid >> 5;
    const int lq   = lane >> 2;     // 0..7
    const int lr   = lane & 3;      // 0..3
    const int wm   = w >> 2;        // 0..1
    const int wn   = w & 3;         // 0..3

    // A-load mapping: 512 float4s; thread handles f = tid, tid+256
    const int ar0 = tid >> 2,         akc0 = (tid & 3) << 2;
    const int ar1 = (tid + 256) >> 2, akc1 = ((tid + 256) & 3) << 2;
    // B-load mapping
    const int bk0 = tid >> 5,         bnc0 = (tid & 31) << 2;
    const int bk1 = (tid + 256) >> 5, bnc1 = ((tid + 256) & 31) << 2;

    const float* Ap0  = A  + (size_t)(brow + ar0) * K + akc0;
    const float* Ap1  = A  + (size_t)(brow + ar1) * K + akc1;
    const float* A2p0 = FUSEA ? (A2 + (size_t)(brow + ar0) * K + akc0) : nullptr;
    const float* A2p1 = FUSEA ? (A2 + (size_t)(brow + ar1) * K + akc1) : nullptr;
    const float* Bp0  = Bm + (size_t)bk0 * N + bcol + bnc0;
    const float* Bp1  = Bm + (size_t)bk1 * N + bcol + bnc1;
    const float* B2p0 = FUSEB ? (B2 + (size_t)bk0 * N + bcol + bnc0) : nullptr;
    const float* B2p1 = FUSEB ? (B2 + (size_t)bk1 * N + bcol + bnc1) : nullptr;

    float acc[4][4][4];
#pragma unroll
    for (int mt = 0; mt < 4; mt++)
#pragma unroll
        for (int nt = 0; nt < 4; nt++)
#pragma unroll
            for (int i = 0; i < 4; i++) acc[mt][nt][i] = 0.f;

    const int nk = K / 16;

    // prologue: stage 0 into buf 0
    {
        float4 a0 = *(const float4*)Ap0;
        float4 a1 = *(const float4*)Ap1;
        if (FUSEA) {
            float4 e0 = *(const float4*)A2p0, e1 = *(const float4*)A2p1;
            a0.x += e0.x; a0.y += e0.y; a0.z += e0.z; a0.w += e0.w;
            a1.x += e1.x; a1.y += e1.y; a1.z += e1.z; a1.w += e1.w;
        }
        a0 = to_tf32_4(a0); a1 = to_tf32_4(a1);
        As[0][akc0+0][ar0] = a0.x; As[0][akc0+1][ar0] = a0.y;
        As[0][akc0+2][ar0] = a0.z; As[0][akc0+3][ar0] = a0.w;
        As[0][akc1+0][ar1] = a1.x; As[0][akc1+1][ar1] = a1.y;
        As[0][akc1+2][ar1] = a1.z; As[0][akc1+3][ar1] = a1.w;
        float4 b0 = *(const float4*)Bp0;
        float4 b1 = *(const float4*)Bp1;
        if (FUSEB) {
            float4 e0 = *(const float4*)B2p0, e1 = *(const float4*)B2p1;
            b0.x += e0.x; b0.y += e0.y; b0.z += e0.z; b0.w += e0.w;
            b1.x += e1.x; b1.y += e1.y; b1.z += e1.z; b1.w += e1.w;
        }
        *(float4*)&Bs[0][bk0][bnc0] = to_tf32_4(b0);
        *(float4*)&Bs[0][bk1][bnc1] = to_tf32_4(b1);
    }
    __syncthreads();

    for (int kt = 0; kt < nk; kt++) {
        const int buf = kt & 1;
        float4 pa0, pa1, pb0, pb1;
        const bool more = (kt + 1 < nk);
        if (more) {
            const int ko = (kt + 1) * 16;
            pa0 = *(const float4*)(Ap0 + ko);
            pa1 = *(const float4*)(Ap1 + ko);
            if (FUSEA) {
                float4 e0 = *(const float4*)(A2p0 + ko);
                float4 e1 = *(const float4*)(A2p1 + ko);
                pa0.x += e0.x; pa0.y += e0.y; pa0.z += e0.z; pa0.w += e0.w;
                pa1.x += e1.x; pa1.y += e1.y; pa1.z += e1.z; pa1.w += e1.w;
            }
            pb0 = *(const float4*)(Bp0 + (size_t)ko * N);
            pb1 = *(const float4*)(Bp1 + (size_t)ko * N);
            if (FUSEB) {
                float4 e0 = *(const float4*)(B2p0 + (size_t)ko * N);
                float4 e1 = *(const float4*)(B2p1 + (size_t)ko * N);
                pb0.x += e0.x; pb0.y += e0.y; pb0.z += e0.z; pb0.w += e0.w;
                pb1.x += e1.x; pb1.y += e1.y; pb1.z += e1.z; pb1.w += e1.w;
            }
        }

        // compute on buf
#pragma unroll
        for (int ks = 0; ks < 2; ks++) {
            const int k = ks * 8;
            uint32_t af[4][4], bf[4][2];
#pragma unroll
            for (int mt = 0; mt < 4; mt++) {
                const int bm = wm * 64 + mt * 16;
                af[mt][0] = fbits(As[buf][k + lr    ][bm + lq    ]);
                af[mt][1] = fbits(As[buf][k + lr    ][bm + lq + 8]);
                af[mt][2] = fbits(As[buf][k + 4 + lr][bm + lq    ]);
                af[mt][3] = fbits(As[buf][k + 4 + lr][bm + lq + 8]);
            }
#pragma unroll
            for (int nt = 0; nt < 4; nt++) {
                const int bn = wn * 32 + nt * 8;
                bf[nt][0] = fbits(Bs[buf][k + lr    ][bn + lq]);
                bf[nt][1] = fbits(Bs[buf][k + 4 + lr][bn + lq]);
            }
#pragma unroll
            for (int mt = 0; mt < 4; mt++)
#pragma unroll
                for (int nt = 0; nt < 4; nt++)
                    mma8(acc[mt][nt], af[mt], bf[nt][0], bf[nt][1]);
        }

        if (more) {
            const int nb = buf ^ 1;
            pa0 = to_tf32_4(pa0); pa1 = to_tf32_4(pa1);
            As[nb][akc0+0][ar0] = pa0.x; As[nb][akc0+1][ar0] = pa0.y;
            As[nb][akc0+2][ar0] = pa0.z; As[nb][akc0+3][ar0] = pa0.w;
            As[nb][akc1+0][ar1] = pa1.x; As[nb][akc1+1][ar1] = pa1.y;
            As[nb][akc1+2][ar1] = pa1.z; As[nb][akc1+3][ar1] = pa1.w;
            *(float4*)&Bs[nb][bk0][bnc0] = to_tf32_4(pb0);
            *(float4*)&Bs[nb][bk1][bnc1] = to_tf32_4(pb1);
            __syncthreads();
        }
    }

    // epilogue
#pragma unroll
    for (int mt = 0; mt < 4; mt++) {
        const int r0 = brow + wm * 64 + mt * 16 + lq;
#pragma unroll
        for (int nt = 0; nt < 4; nt++) {
            const int col = bcol + wn * 32 + nt * 8 + lr * 2;
            *(float2*)(C + (size_t)r0 * N + col)       = make_float2(acc[mt][nt][0], acc[mt][nt][1]);
            *(float2*)(C + (size_t)(r0 + 8) * N + col) = make_float2(acc[mt][nt][2], acc[mt][nt][3]);
        }
    }
}

// ---- merged GEMM launches ----
// weight prep: W12 = w1@w2 (y=0), W46 = w4@w6 (y=1). grid(8,2)
__global__ __launch_bounds__(256, 2) void weight_prep_kernel(
    const float* __restrict__ w1, const float* __restrict__ w2, float* __restrict__ W12,
    const float* __restrict__ w4, const float* __restrict__ w6, float* __restrict__ W46)
{
    __shared__ float As[2][16][APITCH];
    __shared__ float Bs[2][16][APITCH];
    if (blockIdx.y == 0)
        gemm_body<false,false>(As, Bs, w1, nullptr, w2, nullptr, W12, NDH, NH1, blockIdx.x*128, 0);
    else
        gemm_body<false,false>(As, Bs, w4, nullptr, w6, nullptr, W46, NDH, NH1, blockIdx.x*128, 0);
}

// projections: y=0 -> Q2 = q@W12; y=1 -> K3 = k@W46; y=2..5 -> Q3 = q@w3. grid(128,6)
__global__ __launch_bounds__(256, 2) void proj_kernel(
    const float* __restrict__ q, const float* __restrict__ k,
    const float* __restrict__ W12, const float* __restrict__ W46,
    const float* __restrict__ w3,
    float* __restrict__ Q2, float* __restrict__ K3, float* __restrict__ Q3)
{
    __shared__ float As[2][16][APITCH];
    __shared__ float Bs[2][16][APITCH];
    const int y = blockIdx.y;
    if (y == 0)
        gemm_body<false,false>(As, Bs, q, nullptr, W12, nullptr, Q2, NDH, ND, blockIdx.x*128, 0);
    else if (y == 1)
        gemm_body<false,false>(As, Bs, k, nullptr, W46, nullptr, K3, NDH, ND, blockIdx.x*128, 0);
    else
        gemm_body<false,false>(As, Bs, q, nullptr, w3, nullptr, Q3, NDV, ND, blockIdx.x*128, (y-2)*128);
}

// final: out = (ATTN + Q3) @ (w7_top + w7_bot). grid(128,4)
__global__ __launch_bounds__(256, 2) void final_kernel(
    const float* __restrict__ ATTN, const float* __restrict__ Q3,
    const float* __restrict__ w7, float* __restrict__ out)
{
    __shared__ float As[2][16][APITCH];
    __shared__ float Bs[2][16][APITCH];
    gemm_body<true,true>(As, Bs, ATTN, Q3, w7, w7 + (size_t)NDV*NDOUT, out,
                         NDOUT, NDV, blockIdx.x*128, blockIdx.y*128);
}

// ---------------------------------------------------------------------------
// Flash attention (causal) with tf32 mma. BM=BN=64, DH=128, DV=512.
// 256 threads. Full V tile (64x512) resident, loaded via cp.async (overlapped
// with K-stage + QK + softmax).  QK warps: 4(m) x 2(n); PV warps: 2(m) x 4(n)
// ---------------------------------------------------------------------------
#define QPITCH 132   // q*132+r pattern: 132%32=4 -> (4lq+lr) distinct
#define PPITCH 68    // 68%32=4  -> (4lq+lr) distinct
#define VPITCH 520   // r*520+q pattern: 520%32=8 -> (8lr+lq) distinct

__global__ __launch_bounds__(256) void flash_attn_tf32(
    const float* __restrict__ Q2, const float* __restrict__ K3,
    const float* __restrict__ V, float* __restrict__ O)
{
    extern __shared__ float sm[];
    float* Qs   = sm;                       // [64][132]
    float* Ks   = Qs + 64 * QPITCH;         // [64][132]
    float* Ps   = Ks + 64 * QPITCH;         // [64][68]
    float* Vs   = Ps + 64 * PPITCH;         // [64][520]
    float* mrow = Vs + 64 * VPITCH;         // [64]
    float* lrow = mrow + 64;                // [64]
    float* arow = lrow + 64;                // [64]

    const int b   = blockIdx.y;
    const int qt  = (int)gridDim.x - 1 - (int)blockIdx.x;  // long blocks first
    const int q0  = qt * 64;
    const int tid = threadIdx.x;
    const int lane = tid & 31, w = tid >> 5;
    const int lq = lane >> 2, lr = lane & 3;
    const int wmQ = w >> 1, wnQ = w & 1;   // QK: 4m x 2n
    const int wmP = w >> 2, wnP = w & 3;   // PV: 2m x 4n
    const float scale = 0.088388347648318447f;  // 1/sqrt(128)
    const uint32_t vsmem = (uint32_t)__cvta_generic_to_shared(Vs);

    // load Q tile (tf32)
    const float* Qg = Q2 + ((size_t)b * NS + q0) * NDH;
    for (int f = tid; f < 2048; f += 256) {
        int row = f >> 5, kc = (f & 31) << 2;
        *(float4*)&Qs[row * QPITCH + kc] = to_tf32_4(*(const float4*)(Qg + row * NDH + kc));
    }
    if (tid < 64) { mrow[tid] = -1e30f; lrow[tid] = 0.f; }

    float oacc[2][16][4];
#pragma unroll
    for (int mt = 0; mt < 2; mt++)
#pragma unroll
        for (int nt = 0; nt < 16; nt++)
#pragma unroll
            for (int i = 0; i < 4; i++) oacc[mt][nt][i] = 0.f;

    for (int kt = 0; kt <= qt; kt++) {
        const int k0 = kt * 64;
        __syncthreads();   // prev iteration's PV readers done with Ks/Vs/Ps

        // async V tile load (raw fp32 bits; mma truncates -> compensated in epilogue)
        {
            const float* Vg = V + ((size_t)b * NS + k0) * NDV;
#pragma unroll
            for (int f = tid; f < 8192; f += 256) {
                int row = f >> 7, nc = (f & 127) << 2;
                uint32_t dst = vsmem + (uint32_t)(row * VPITCH + nc) * 4u;
                asm volatile("cp.async.cg.shared.global [%0], [%1], 16;\n"
                             :: "r"(dst), "l"(Vg + (size_t)row * NDV + nc));
            }
            asm volatile("cp.async.commit_group;\n" ::: "memory");
        }

        const float* Kg = K3 + ((size_t)b * NS + k0) * NDH;
        for (int f = tid; f < 2048; f += 256) {
            int row = f >> 5, kc = (f & 31) << 2;
            *(float4*)&Ks[row * QPITCH + kc] = to_tf32_4(*(const float4*)(Kg + row * NDH + kc));
        }
        __syncthreads();

        // ---- S = Q @ K^T  (warp: 16 rows x 32 cols) ----
        float sacc[4][4];
#pragma unroll
        for (int nt = 0; nt < 4; nt++)
#pragma unroll
            for (int i = 0; i < 4; i++) sacc[nt][i] = 0.f;

#pragma unroll
        for (int ks = 0; ks < 16; ks++) {
            const int k = ks * 8;
            uint32_t af[4];
            const int rq = (wmQ * 16 + lq) * QPITCH;
            af[0] = fbits(Qs[rq            + k + lr]);
            af[1] = fbits(Qs[rq + 8*QPITCH + k + lr]);
            af[2] = fbits(Qs[rq            + k + 4 + lr]);
            af[3] = fbits(Qs[rq + 8*QPITCH + k + 4 + lr]);
#pragma unroll
            for (int nt = 0; nt < 4; nt++) {
                const int rk = (wnQ * 32 + nt * 8 + lq) * QPITCH;
                uint32_t b0 = fbits(Ks[rk + k + lr]);
                uint32_t b1 = fbits(Ks[rk + k + 4 + lr]);
                mma8(sacc[nt], af, b0, b1);
            }
        }
        // scale + causal mask + store to Ps (fp32)
        {
            const bool diag = (kt == qt);
            const int rloc0 = wmQ * 16 + lq;
            const int grow0 = q0 + rloc0, grow1 = grow0 + 8;
#pragma unroll
            for (int nt = 0; nt < 4; nt++) {
                const int col = wnQ * 32 + nt * 8 + lr * 2;
                const int gc0 = k0 + col, gc1 = gc0 + 1;
                float v0 = sacc[nt][0] * scale;
                float v1 = sacc[nt][1] * scale;
                float v2 = sacc[nt][2] * scale;
                float v3 = sacc[nt][3] * scale;
                if (diag) {
                    if (gc0 > grow0) v0 = -1e30f;
                    if (gc1 > grow0) v1 = -1e30f;
                    if (gc0 > grow1) v2 = -1e30f;
                    if (gc1 > grow1) v3 = -1e30f;
                }
                Ps[rloc0 * PPITCH + col]           = v0;
                Ps[rloc0 * PPITCH + col + 1]       = v1;
                Ps[(rloc0 + 8) * PPITCH + col]     = v2;
                Ps[(rloc0 + 8) * PPITCH + col + 1] = v3;
            }
        }
        __syncthreads();

        // ---- online softmax on Ps (4 threads/row, 16 cols each) ----
        {
            const int row = tid >> 2, g = tid & 3;
            float mx = -1e30f;
#pragma unroll
            for (int c = 0; c < 16; c++) mx = fmaxf(mx, Ps[row * PPITCH + g * 16 + c]);
            mx = fmaxf(mx, __shfl_xor_sync(0xffffffffu, mx, 1));
            mx = fmaxf(mx, __shfl_xor_sync(0xffffffffu, mx, 2));
            const float mold = mrow[row];
            const float mnew = fmaxf(mold, mx);
            const float al   = __expf(mold - mnew);
            float sum = 0.f;
#pragma unroll
            for (int c = 0; c < 16; c++) {
                const int idx = row * PPITCH + g * 16 + c;
                float p = __expf(Ps[idx] - mnew);
                Ps[idx] = to_tf32(p);
                sum += p;
            }
            sum += __shfl_xor_sync(0xffffffffu, sum, 1);
            sum += __shfl_xor_sync(0xffffffffu, sum, 2);
            if (g == 0) {
                mrow[row] = mnew;
                lrow[row] = lrow[row] * al + sum;
                arow[row] = al;
            }
        }
        asm volatile("cp.async.wait_group 0;\n" ::: "memory");
        __syncthreads();   // Ps + V visible to all

        // ---- rescale O accumulators, then O += P @ V ----
        {
            const int rb = wmP * 32;
            const float al00 = arow[rb + lq];
            const float al01 = arow[rb + lq + 8];
            const float al10 = arow[rb + 16 + lq];
            const float al11 = arow[rb + 16 + lq + 8];
#pragma unroll
            for (int nt = 0; nt < 16; nt++) {
                oacc[0][nt][0] *= al00; oacc[0][nt][1] *= al00;
                oacc[0][nt][2] *= al01; oacc[0][nt][3] *= al01;
                oacc[1][nt][0] *= al10; oacc[1][nt][1] *= al10;
                oacc[1][nt][2] *= al11; oacc[1][nt][3] *= al11;
            }
#pragma unroll
            for (int ks = 0; ks < 8; ks++) {
                const int k = ks * 8;
                uint32_t af[2][4];
#pragma unroll
                for (int mt = 0; mt < 2; mt++) {
                    const int rp = (rb + mt * 16 + lq) * PPITCH;
                    af[mt][0] = fbits(Ps[rp             + k + lr]);
                    af[mt][1] = fbits(Ps[rp + 8*PPITCH  + k + lr]);
                    af[mt][2] = fbits(Ps[rp             + k + 4 + lr]);
                    af[mt][3] = fbits(Ps[rp + 8*PPITCH  + k + 4 + lr]);
                }
#pragma unroll
                for (int nt = 0; nt < 16; nt++) {
                    const int cb = wnP * 128 + nt * 8 + lq;
                    uint32_t b0 = fbits(Vs[(k + lr) * VPITCH + cb]);
                    uint32_t b1 = fbits(Vs[(k + 4 + lr) * VPITCH + cb]);
                    mma8(oacc[0][nt], af[0], b0, b1);
                    mma8(oacc[1][nt], af[1], b0, b1);
                }
            }
        }
    }

    __syncthreads();
    // epilogue: normalize and store.  comp = 1 + 2^-12 cancels the mean
    // downward bias of feeding raw fp32 V bits to the tf32 mma (truncation).
    {
        const float comp = 1.000244140625f;
        const int rb = wmP * 32;
        float li[2][2];
        li[0][0] = comp / lrow[rb + lq];
        li[0][1] = comp / lrow[rb + lq + 8];
        li[1][0] = comp / lrow[rb + 16 + lq];
        li[1][1] = comp / lrow[rb + 16 + lq + 8];
#pragma unroll
        for (int mt = 0; mt < 2; mt++) {
            const int gr = q0 + rb + mt * 16 + lq;
#pragma unroll
            for (int nt = 0; nt < 16; nt++) {
                const int col = wnP * 128 + nt * 8 + lr * 2;
                *(float2*)(O + ((size_t)b * NS + gr) * NDV + col) =
                    make_float2(oacc[mt][nt][0] * li[mt][0], oacc[mt][nt][1] * li[mt][0]);
                *(float2*)(O + ((size_t)b * NS + gr + 8) * NDV + col) =
                    make_float2(oacc[mt][nt][2] * li[mt][1], oacc[mt][nt][3] * li[mt][1]);
            }
        }
    }
}

// ---------------------------------------------------------------------------
extern "C" void kernel_launch(void* const* d_in, const int* in_sizes, int n_in,
                              void* d_out, int out_size)
{
    const float* q  = (const float*)d_in[0];
    const float* k  = (const float*)d_in[1];
    const float* v  = (const float*)d_in[2];
    const float* w1 = (const float*)d_in[3];
    const float* w2 = (const float*)d_in[4];
    const float* w3 = (const float*)d_in[5];
    const float* w4 = (const float*)d_in[6];
    const float* w6 = (const float*)d_in[7];
    const float* w7 = (const float*)d_in[8];
    float* out = (float*)d_out;

    // cache symbol addresses + one-time attribute setup across calls
    static float *W12 = nullptr, *W46, *Q2, *K3, *Q3, *ATTN;
    static bool init_done = false;
    if (!init_done) {
        cudaGetSymbolAddress((void**)&W12,  g_W12);
        cudaGetSymbolAddress((void**)&W46,  g_W46);
        cudaGetSymbolAddress((void**)&Q2,   g_Q2);
        cudaGetSymbolAddress((void**)&K3,   g_K3);
        cudaGetSymbolAddress((void**)&Q3,   g_Q3);
        cudaGetSymbolAddress((void**)&ATTN, g_ATTN);
        size_t smem_attr = (size_t)(64*QPITCH + 64*QPITCH + 64*PPITCH + 64*VPITCH + 192) * sizeof(float);
        cudaFuncSetAttribute(flash_attn_tf32, cudaFuncAttributeMaxDynamicSharedMemorySize, (int)smem_attr);
        init_done = true;
    }

    // 1) weight prep:  W12 = w1@w2, W46 = w4@w6   (one launch, grid 8x2)
    weight_prep_kernel<<<dim3(ND/128, 2), 256>>>(w1, w2, W12, w4, w6, W46);

    // 2) all projections in one launch: Q2 = q@W12, K3 = k@W46, Q3 = q@w3
    proj_kernel<<<dim3(NM/128, 6), 256>>>(q, k, W12, W46, w3, Q2, K3, Q3);

    // 3) causal flash attention (tf32 tensor cores)
    size_t smem = (size_t)(64*QPITCH + 64*QPITCH + 64*PPITCH + 64*VPITCH + 192) * sizeof(float);
    flash_attn_tf32<<<dim3(NS/64, NB), 256, smem>>>(Q2, K3, v, ATTN);

    // 4) final: out = (ATTN + Q3) @ (w7_top + w7_bot)   (wsum fused into B-stage)
    final_kernel<<<dim3(NM/128, NDOUT/128), 256>>>(ATTN, Q3, w7, out);
}

// round 5
// speedup vs baseline: 3.8004x; 1.0488x over previous
#include <cuda_runtime.h>
#include <math.h>
#include <stdint.h>

#define NB 8
#define NS 2048
#define ND 1024
#define NH1 512
#define NDH 128
#define NDV 512
#define NDOUT 512
#define NM (NB*NS)   // 16384

// scratch (device globals: allocation-free per harness rules)
__device__ float g_W12[ND*NDH];
__device__ float g_W46[ND*NDH];
__device__ float g_Q2[(size_t)NM*NDH];
__device__ float g_K3[(size_t)NM*NDH];
__device__ float g_Q3[(size_t)NM*NDV];
__device__ float g_ATTN[(size_t)NM*NDV];

// ---------------------------------------------------------------------------
// helpers
// ---------------------------------------------------------------------------
__device__ __forceinline__ float to_tf32(float x) {
    float r;
    asm("cvt.rna.tf32.f32 %0, %1;" : "=f"(r) : "f"(x));
    return r;
}
__device__ __forceinline__ float4 to_tf32_4(float4 v) {
    v.x = to_tf32(v.x); v.y = to_tf32(v.y);
    v.z = to_tf32(v.z); v.w = to_tf32(v.w);
    return v;
}
__device__ __forceinline__ uint32_t fbits(float x) { return __float_as_uint(x); }

// D += A@B  (m16n8k8, tf32, row.col)
__device__ __forceinline__ void mma8(float d[4], const uint32_t a[4],
                                     uint32_t b0, uint32_t b1) {
    asm volatile(
        "mma.sync.aligned.m16n8k8.row.col.f32.tf32.tf32.f32 "
        "{%0,%1,%2,%3},{%4,%5,%6,%7},{%8,%9},{%0,%1,%2,%3};"
        : "+f"(d[0]), "+f"(d[1]), "+f"(d[2]), "+f"(d[3])
        : "r"(a[0]), "r"(a[1]), "r"(a[2]), "r"(a[3]), "r"(b0), "r"(b1));
}

// ---------------------------------------------------------------------------
// TF32 GEMM body: C[*,N] tile at (brow,bcol) = (A (+A2)) @ (B (+B2))
// row-major; tile 128x128, BK=16, 256 threads = 8 warps (2m x 4n)
// ---------------------------------------------------------------------------
#define APITCH 136   // 136 % 32 == 8 -> conflict-free (8*lr + lq) fragment pattern

template<bool FUSEA, bool FUSEB>
__device__ __forceinline__ void gemm_body(
    float (*As)[16][APITCH], float (*Bs)[16][APITCH],
    const float* __restrict__ A, const float* __restrict__ A2,
    const float* __restrict__ Bm, const float* __restrict__ B2,
    float* __restrict__ C, int N, int K, int brow, int bcol)
{
    const int tid  = threadIdx.x;
    const int lane = tid & 31;
    const int w    = tid >> 5;
    const int lq   = lane >> 2;     // 0..7
    const int lr   = lane & 3;      // 0..3
    const int wm   = w >> 2;        // 0..1
    const int wn   = w & 3;         // 0..3

    // A-load mapping: 512 float4s; thread handles f = tid, tid+256
    const int ar0 = tid >> 2,         akc0 = (tid & 3) << 2;
    const int ar1 = (tid + 256) >> 2, akc1 = ((tid + 256) & 3) << 2;
    // B-load mapping
    const int bk0 = tid >> 5,         bnc0 = (tid & 31) << 2;
    const int bk1 = (tid + 256) >> 5, bnc1 = ((tid + 256) & 31) << 2;

    const float* Ap0  = A  + (size_t)(brow + ar0) * K + akc0;
    const float* Ap1  = A  + (size_t)(brow + ar1) * K + akc1;
    const float* A2p0 = FUSEA ? (A2 + (size_t)(brow + ar0) * K + akc0) : nullptr;
    const float* A2p1 = FUSEA ? (A2 + (size_t)(brow + ar1) * K + akc1) : nullptr;
    const float* Bp0  = Bm + (size_t)bk0 * N + bcol + bnc0;
    const float* Bp1  = Bm + (size_t)bk1 * N + bcol + bnc1;
    const float* B2p0 = FUSEB ? (B2 + (size_t)bk0 * N + bcol + bnc0) : nullptr;
    const float* B2p1 = FUSEB ? (B2 + (size_t)bk1 * N + bcol + bnc1) : nullptr;

    float acc[4][4][4];
#pragma unroll
    for (int mt = 0; mt < 4; mt++)
#pragma unroll
        for (int nt = 0; nt < 4; nt++)
#pragma unroll
            for (int i = 0; i < 4; i++) acc[mt][nt][i] = 0.f;

    const int nk = K / 16;

    // prologue: stage 0 into buf 0
    {
        float4 a0 = *(const float4*)Ap0;
        float4 a1 = *(const float4*)Ap1;
        if (FUSEA) {
            float4 e0 = *(const float4*)A2p0, e1 = *(const float4*)A2p1;
            a0.x += e0.x; a0.y += e0.y; a0.z += e0.z; a0.w += e0.w;
            a1.x += e1.x; a1.y += e1.y; a1.z += e1.z; a1.w += e1.w;
        }
        a0 = to_tf32_4(a0); a1 = to_tf32_4(a1);
        As[0][akc0+0][ar0] = a0.x; As[0][akc0+1][ar0] = a0.y;
        As[0][akc0+2][ar0] = a0.z; As[0][akc0+3][ar0] = a0.w;
        As[0][akc1+0][ar1] = a1.x; As[0][akc1+1][ar1] = a1.y;
        As[0][akc1+2][ar1] = a1.z; As[0][akc1+3][ar1] = a1.w;
        float4 b0 = *(const float4*)Bp0;
        float4 b1 = *(const float4*)Bp1;
        if (FUSEB) {
            float4 e0 = *(const float4*)B2p0, e1 = *(const float4*)B2p1;
            b0.x += e0.x; b0.y += e0.y; b0.z += e0.z; b0.w += e0.w;
            b1.x += e1.x; b1.y += e1.y; b1.z += e1.z; b1.w += e1.w;
        }
        *(float4*)&Bs[0][bk0][bnc0] = to_tf32_4(b0);
        *(float4*)&Bs[0][bk1][bnc1] = to_tf32_4(b1);
    }
    __syncthreads();

    for (int kt = 0; kt < nk; kt++) {
        const int buf = kt & 1;
        float4 pa0, pa1, pb0, pb1;
        const bool more = (kt + 1 < nk);
        if (more) {
            const int ko = (kt + 1) * 16;
            pa0 = *(const float4*)(Ap0 + ko);
            pa1 = *(const float4*)(Ap1 + ko);
            if (FUSEA) {
                float4 e0 = *(const float4*)(A2p0 + ko);
                float4 e1 = *(const float4*)(A2p1 + ko);
                pa0.x += e0.x; pa0.y += e0.y; pa0.z += e0.z; pa0.w += e0.w;
                pa1.x += e1.x; pa1.y += e1.y; pa1.z += e1.z; pa1.w += e1.w;
            }
            pb0 = *(const float4*)(Bp0 + (size_t)ko * N);
            pb1 = *(const float4*)(Bp1 + (size_t)ko * N);
            if (FUSEB) {
                float4 e0 = *(const float4*)(B2p0 + (size_t)ko * N);
                float4 e1 = *(const float4*)(B2p1 + (size_t)ko * N);
                pb0.x += e0.x; pb0.y += e0.y; pb0.z += e0.z; pb0.w += e0.w;
                pb1.x += e1.x; pb1.y += e1.y; pb1.z += e1.z; pb1.w += e1.w;
            }
        }

        // compute on buf
#pragma unroll
        for (int ks = 0; ks < 2; ks++) {
            const int k = ks * 8;
            uint32_t af[4][4], bf[4][2];
#pragma unroll
            for (int mt = 0; mt < 4; mt++) {
                const int bm = wm * 64 + mt * 16;
                af[mt][0] = fbits(As[buf][k + lr    ][bm + lq    ]);
                af[mt][1] = fbits(As[buf][k + lr    ][bm + lq + 8]);
                af[mt][2] = fbits(As[buf][k + 4 + lr][bm + lq    ]);
                af[mt][3] = fbits(As[buf][k + 4 + lr][bm + lq + 8]);
            }
#pragma unroll
            for (int nt = 0; nt < 4; nt++) {
                const int bn = wn * 32 + nt * 8;
                bf[nt][0] = fbits(Bs[buf][k + lr    ][bn + lq]);
                bf[nt][1] = fbits(Bs[buf][k + 4 + lr][bn + lq]);
            }
#pragma unroll
            for (int mt = 0; mt < 4; mt++)
#pragma unroll
                for (int nt = 0; nt < 4; nt++)
                    mma8(acc[mt][nt], af[mt], bf[nt][0], bf[nt][1]);
        }

        if (more) {
            const int nb = buf ^ 1;
            pa0 = to_tf32_4(pa0); pa1 = to_tf32_4(pa1);
            As[nb][akc0+0][ar0] = pa0.x; As[nb][akc0+1][ar0] = pa0.y;
            As[nb][akc0+2][ar0] = pa0.z; As[nb][akc0+3][ar0] = pa0.w;
            As[nb][akc1+0][ar1] = pa1.x; As[nb][akc1+1][ar1] = pa1.y;
            As[nb][akc1+2][ar1] = pa1.z; As[nb][akc1+3][ar1] = pa1.w;
            *(float4*)&Bs[nb][bk0][bnc0] = to_tf32_4(pb0);
            *(float4*)&Bs[nb][bk1][bnc1] = to_tf32_4(pb1);
            __syncthreads();
        }
    }

    // epilogue
#pragma unroll
    for (int mt = 0; mt < 4; mt++) {
        const int r0 = brow + wm * 64 + mt * 16 + lq;
#pragma unroll
        for (int nt = 0; nt < 4; nt++) {
            const int col = bcol + wn * 32 + nt * 8 + lr * 2;
            *(float2*)(C + (size_t)r0 * N + col)       = make_float2(acc[mt][nt][0], acc[mt][nt][1]);
            *(float2*)(C + (size_t)(r0 + 8) * N + col) = make_float2(acc[mt][nt][2], acc[mt][nt][3]);
        }
    }
}

// ---- merged GEMM launches ----
// weight prep: W12 = w1@w2 (y=0), W46 = w4@w6 (y=1). grid(8,2)
__global__ __launch_bounds__(256, 2) void weight_prep_kernel(
    const float* __restrict__ w1, const float* __restrict__ w2, float* __restrict__ W12,
    const float* __restrict__ w4, const float* __restrict__ w6, float* __restrict__ W46)
{
    __shared__ float As[2][16][APITCH];
    __shared__ float Bs[2][16][APITCH];
    if (blockIdx.y == 0)
        gemm_body<false,false>(As, Bs, w1, nullptr, w2, nullptr, W12, NDH, NH1, blockIdx.x*128, 0);
    else
        gemm_body<false,false>(As, Bs, w4, nullptr, w6, nullptr, W46, NDH, NH1, blockIdx.x*128, 0);
}

// projections: y=0 -> Q2 = q@W12; y=1 -> K3 = k@W46; y=2..5 -> Q3 = q@w3. grid(128,6)
__global__ __launch_bounds__(256, 2) void proj_kernel(
    const float* __restrict__ q, const float* __restrict__ k,
    const float* __restrict__ W12, const float* __restrict__ W46,
    const float* __restrict__ w3,
    float* __restrict__ Q2, float* __restrict__ K3, float* __restrict__ Q3)
{
    __shared__ float As[2][16][APITCH];
    __shared__ float Bs[2][16][APITCH];
    const int y = blockIdx.y;
    if (y == 0)
        gemm_body<false,false>(As, Bs, q, nullptr, W12, nullptr, Q2, NDH, ND, blockIdx.x*128, 0);
    else if (y == 1)
        gemm_body<false,false>(As, Bs, k, nullptr, W46, nullptr, K3, NDH, ND, blockIdx.x*128, 0);
    else
        gemm_body<false,false>(As, Bs, q, nullptr, w3, nullptr, Q3, NDV, ND, blockIdx.x*128, (y-2)*128);
}

// final: out = (ATTN + Q3) @ (w7_top + w7_bot). grid(128,4)
__global__ __launch_bounds__(256, 2) void final_kernel(
    const float* __restrict__ ATTN, const float* __restrict__ Q3,
    const float* __restrict__ w7, float* __restrict__ out)
{
    __shared__ float As[2][16][APITCH];
    __shared__ float Bs[2][16][APITCH];
    gemm_body<true,true>(As, Bs, ATTN, Q3, w7, w7 + (size_t)NDV*NDOUT, out,
                         NDOUT, NDV, blockIdx.x*128, blockIdx.y*128);
}

// ---------------------------------------------------------------------------
// Flash attention (causal) with tf32 mma. BM=BN=64, DH=128, DV=512.
// 512 threads (16 warps), 1 CTA/SM (smem-bound). Full V tile resident.
// K and V staged via cp.async (separate groups; K awaited before QK, V before PV).
//   QK warps: 4(m) x 4(n), warp tile 16x16; PV warps: 2(m) x 8(n), warp tile 32x64
// ---------------------------------------------------------------------------
#define QPITCH 132   // q*132+r pattern: 132%32=4 -> (4lq+lr) distinct
#define PPITCH 68    // 68%32=4  -> (4lq+lr) distinct
#define VPITCH 520   // r*520+q pattern: 520%32=8 -> (8lr+lq) distinct

__global__ __launch_bounds__(512) void flash_attn_tf32(
    const float* __restrict__ Q2, const float* __restrict__ K3,
    const float* __restrict__ V, float* __restrict__ O)
{
    extern __shared__ float sm[];
    float* Qs   = sm;                       // [64][132]
    float* Ks   = Qs + 64 * QPITCH;         // [64][132]
    float* Ps   = Ks + 64 * QPITCH;         // [64][68]
    float* Vs   = Ps + 64 * PPITCH;         // [64][520]
    float* mrow = Vs + 64 * VPITCH;         // [64]
    float* lrow = mrow + 64;                // [64]
    float* arow = lrow + 64;                // [64]

    const int b   = blockIdx.y;
    const int qt  = (int)gridDim.x - 1 - (int)blockIdx.x;  // long blocks first
    const int q0  = qt * 64;
    const int tid = threadIdx.x;
    const int lane = tid & 31, w = tid >> 5;    // w: 0..15
    const int lq = lane >> 2, lr = lane & 3;
    const int wmQ = w >> 2, wnQ = w & 3;   // QK: 4m x 4n
    const int wmP = w >> 3, wnP = w & 7;   // PV: 2m x 8n
    const float scale = 0.088388347648318447f;  // 1/sqrt(128)
    const uint32_t ksmem = (uint32_t)__cvta_generic_to_shared(Ks);
    const uint32_t vsmem = (uint32_t)__cvta_generic_to_shared(Vs);

    // load Q tile (tf32, rna)
    const float* Qg = Q2 + ((size_t)b * NS + q0) * NDH;
    for (int f = tid; f < 2048; f += 512) {
        int row = f >> 5, kc = (f & 31) << 2;
        *(float4*)&Qs[row * QPITCH + kc] = to_tf32_4(*(const float4*)(Qg + row * NDH + kc));
    }
    if (tid < 64) { mrow[tid] = -1e30f; lrow[tid] = 0.f; }

    float oacc[2][8][4];
#pragma unroll
    for (int mt = 0; mt < 2; mt++)
#pragma unroll
        for (int nt = 0; nt < 8; nt++)
#pragma unroll
            for (int i = 0; i < 4; i++) oacc[mt][nt][i] = 0.f;

    for (int kt = 0; kt <= qt; kt++) {
        const int k0 = kt * 64;
        __syncthreads();   // prev iteration's readers done with Ks/Vs/Ps

        // async K tile (group 0): raw fp32 bits; mma truncation ~= benign
        // uniform score scale (1 - 2^-12), self-normalized by softmax.
        {
            const float* Kg = K3 + ((size_t)b * NS + k0) * NDH;
#pragma unroll
            for (int f = tid; f < 2048; f += 512) {
                int row = f >> 5, kc = (f & 31) << 2;
                uint32_t dst = ksmem + (uint32_t)(row * QPITCH + kc) * 4u;
                asm volatile("cp.async.cg.shared.global [%0], [%1], 16;\n"
                             :: "r"(dst), "l"(Kg + (size_t)row * NDH + kc));
            }
            asm volatile("cp.async.commit_group;\n" ::: "memory");
        }
        // async V tile (group 1): truncation compensated in epilogue
        {
            const float* Vg = V + ((size_t)b * NS + k0) * NDV;
#pragma unroll
            for (int f = tid; f < 8192; f += 512) {
                int row = f >> 7, nc = (f & 127) << 2;
                uint32_t dst = vsmem + (uint32_t)(row * VPITCH + nc) * 4u;
                asm volatile("cp.async.cg.shared.global [%0], [%1], 16;\n"
                             :: "r"(dst), "l"(Vg + (size_t)row * NDV + nc));
            }
            asm volatile("cp.async.commit_group;\n" ::: "memory");
        }

        asm volatile("cp.async.wait_group 1;\n" ::: "memory");  // K ready
        __syncthreads();

        // ---- S = Q @ K^T  (warp: 16 rows x 16 cols) ----
        float sacc[2][4];
#pragma unroll
        for (int nt = 0; nt < 2; nt++)
#pragma unroll
            for (int i = 0; i < 4; i++) sacc[nt][i] = 0.f;

#pragma unroll
        for (int ks = 0; ks < 16; ks++) {
            const int k = ks * 8;
            uint32_t af[4];
            const int rq = (wmQ * 16 + lq) * QPITCH;
            af[0] = fbits(Qs[rq            + k + lr]);
            af[1] = fbits(Qs[rq + 8*QPITCH + k + lr]);
            af[2] = fbits(Qs[rq            + k + 4 + lr]);
            af[3] = fbits(Qs[rq + 8*QPITCH + k + 4 + lr]);
#pragma unroll
            for (int nt = 0; nt < 2; nt++) {
                const int rk = (wnQ * 16 + nt * 8 + lq) * QPITCH;
                uint32_t b0 = fbits(Ks[rk + k + lr]);
                uint32_t b1 = fbits(Ks[rk + k + 4 + lr]);
                mma8(sacc[nt], af, b0, b1);
            }
        }
        // scale + causal mask + store to Ps (fp32)
        {
            const bool diag = (kt == qt);
            const int rloc0 = wmQ * 16 + lq;
            const int grow0 = q0 + rloc0, grow1 = grow0 + 8;
#pragma unroll
            for (int nt = 0; nt < 2; nt++) {
                const int col = wnQ * 16 + nt * 8 + lr * 2;
                const int gc0 = k0 + col, gc1 = gc0 + 1;
                float v0 = sacc[nt][0] * scale;
                float v1 = sacc[nt][1] * scale;
                float v2 = sacc[nt][2] * scale;
                float v3 = sacc[nt][3] * scale;
                if (diag) {
                    if (gc0 > grow0) v0 = -1e30f;
                    if (gc1 > grow0) v1 = -1e30f;
                    if (gc0 > grow1) v2 = -1e30f;
                    if (gc1 > grow1) v3 = -1e30f;
                }
                Ps[rloc0 * PPITCH + col]           = v0;
                Ps[rloc0 * PPITCH + col + 1]       = v1;
                Ps[(rloc0 + 8) * PPITCH + col]     = v2;
                Ps[(rloc0 + 8) * PPITCH + col + 1] = v3;
            }
        }
        __syncthreads();

        // ---- online softmax on Ps (8 threads/row, 8 cols each) ----
        {
            const int row = tid >> 3, g = tid & 7;
            float mx = -1e30f;
#pragma unroll
            for (int c = 0; c < 8; c++) mx = fmaxf(mx, Ps[row * PPITCH + g * 8 + c]);
            mx = fmaxf(mx, __shfl_xor_sync(0xffffffffu, mx, 1));
            mx = fmaxf(mx, __shfl_xor_sync(0xffffffffu, mx, 2));
            mx = fmaxf(mx, __shfl_xor_sync(0xffffffffu, mx, 4));
            const float mold = mrow[row];
            const float mnew = fmaxf(mold, mx);
            const float al   = __expf(mold - mnew);
            float sum = 0.f;
#pragma unroll
            for (int c = 0; c < 8; c++) {
                const int idx = row * PPITCH + g * 8 + c;
                float p = __expf(Ps[idx] - mnew);
                Ps[idx] = to_tf32(p);
                sum += p;
            }
            sum += __shfl_xor_sync(0xffffffffu, sum, 1);
            sum += __shfl_xor_sync(0xffffffffu, sum, 2);
            sum += __shfl_xor_sync(0xffffffffu, sum, 4);
            if (g == 0) {
                mrow[row] = mnew;
                lrow[row] = lrow[row] * al + sum;
                arow[row] = al;
            }
        }
        asm volatile("cp.async.wait_group 0;\n" ::: "memory");  // V ready
        __syncthreads();   // Ps + V visible to all

        // ---- rescale O accumulators, then O += P @ V ----
        {
            const int rb = wmP * 32;
            const float al00 = arow[rb + lq];
            const float al01 = arow[rb + lq + 8];
            const float al10 = arow[rb + 16 + lq];
            const float al11 = arow[rb + 16 + lq + 8];
#pragma unroll
            for (int nt = 0; nt < 8; nt++) {
                oacc[0][nt][0] *= al00; oacc[0][nt][1] *= al00;
                oacc[0][nt][2] *= al01; oacc[0][nt][3] *= al01;
                oacc[1][nt][0] *= al10; oacc[1][nt][1] *= al10;
                oacc[1][nt][2] *= al11; oacc[1][nt][3] *= al11;
            }
#pragma unroll
            for (int ks = 0; ks < 8; ks++) {
                const int k = ks * 8;
                uint32_t af[2][4];
#pragma unroll
                for (int mt = 0; mt < 2; mt++) {
                    const int rp = (rb + mt * 16 + lq) * PPITCH;
                    af[mt][0] = fbits(Ps[rp             + k + lr]);
                    af[mt][1] = fbits(Ps[rp + 8*PPITCH  + k + lr]);
                    af[mt][2] = fbits(Ps[rp             + k + 4 + lr]);
                    af[mt][3] = fbits(Ps[rp + 8*PPITCH  + k + 4 + lr]);
                }
#pragma unroll
                for (int nt = 0; nt < 8; nt++) {
                    const int cb = wnP * 64 + nt * 8 + lq;
                    uint32_t b0 = fbits(Vs[(k + lr) * VPITCH + cb]);
                    uint32_t b1 = fbits(Vs[(k + 4 + lr) * VPITCH + cb]);
                    mma8(oacc[0][nt], af[0], b0, b1);
                    mma8(oacc[1][nt], af[1], b0, b1);
                }
            }
        }
    }

    __syncthreads();
    // epilogue: normalize and store.  comp = 1 + 2^-12 cancels the mean
    // downward bias of feeding raw fp32 V bits to the tf32 mma (truncation).
    {
        const float comp = 1.000244140625f;
        const int rb = wmP * 32;
        float li[2][2];
        li[0][0] = comp / lrow[rb + lq];
        li[0][1] = comp / lrow[rb + lq + 8];
        li[1][0] = comp / lrow[rb + 16 + lq];
        li[1][1] = comp / lrow[rb + 16 + lq + 8];
#pragma unroll
        for (int mt = 0; mt < 2; mt++) {
            const int gr = q0 + rb + mt * 16 + lq;
#pragma unroll
            for (int nt = 0; nt < 8; nt++) {
                const int col = wnP * 64 + nt * 8 + lr * 2;
                *(float2*)(O + ((size_t)b * NS + gr) * NDV + col) =
                    make_float2(oacc[mt][nt][0] * li[mt][0], oacc[mt][nt][1] * li[mt][0]);
                *(float2*)(O + ((size_t)b * NS + gr + 8) * NDV + col) =
                    make_float2(oacc[mt][nt][2] * li[mt][1], oacc[mt][nt][3] * li[mt][1]);
            }
        }
    }
}

// ---------------------------------------------------------------------------
extern "C" void kernel_launch(void* const* d_in, const int* in_sizes, int n_in,
                              void* d_out, int out_size)
{
    const float* q  = (const float*)d_in[0];
    const float* k  = (const float*)d_in[1];
    const float* v  = (const float*)d_in[2];
    const float* w1 = (const float*)d_in[3];
    const float* w2 = (const float*)d_in[4];
    const float* w3 = (const float*)d_in[5];
    const float* w4 = (const float*)d_in[6];
    const float* w6 = (const float*)d_in[7];
    const float* w7 = (const float*)d_in[8];
    float* out = (float*)d_out;

    // cache symbol addresses + one-time attribute setup across calls
    static float *W12 = nullptr, *W46, *Q2, *K3, *Q3, *ATTN;
    static bool init_done = false;
    if (!init_done) {
        cudaGetSymbolAddress((void**)&W12,  g_W12);
        cudaGetSymbolAddress((void**)&W46,  g_W46);
        cudaGetSymbolAddress((void**)&Q2,   g_Q2);
        cudaGetSymbolAddress((void**)&K3,   g_K3);
        cudaGetSymbolAddress((void**)&Q3,   g_Q3);
        cudaGetSymbolAddress((void**)&ATTN, g_ATTN);
        size_t smem_attr = (size_t)(64*QPITCH + 64*QPITCH + 64*PPITCH + 64*VPITCH + 192) * sizeof(float);
        cudaFuncSetAttribute(flash_attn_tf32, cudaFuncAttributeMaxDynamicSharedMemorySize, (int)smem_attr);
        init_done = true;
    }

    // 1) weight prep:  W12 = w1@w2, W46 = w4@w6   (one launch, grid 8x2)
    weight_prep_kernel<<<dim3(ND/128, 2), 256>>>(w1, w2, W12, w4, w6, W46);

    // 2) all projections in one launch: Q2 = q@W12, K3 = k@W46, Q3 = q@w3
    proj_kernel<<<dim3(NM/128, 6), 256>>>(q, k, W12, W46, w3, Q2, K3, Q3);

    // 3) causal flash attention (tf32 tensor cores, 512 threads)
    size_t smem = (size_t)(64*QPITCH + 64*QPITCH + 64*PPITCH + 64*VPITCH + 192) * sizeof(float);
    flash_attn_tf32<<<dim3(NS/64, NB), 512, smem>>>(Q2, K3, v, ATTN);

    // 4) final: out = (ATTN + Q3) @ (w7_top + w7_bot)   (wsum fused into B-stage)
    final_kernel<<<dim3(NM/128, NDOUT/128), 256>>>(ATTN, Q3, w7, out);
}